// round 4
// baseline (speedup 1.0000x reference)
#include <cuda_runtime.h>
#include <math_constants.h>
#include <math.h>
#include <cstdint>

#define TOKENS 16384
#define HIDDEN 7168
#define NEXP   256
#define TOPK   8
#define KC     32
#define NCHUNK (HIDDEN / KC)   // 224
#define TAU    1e-4f

// SMEM stage layout (bytes): Ah 16K | Al 16K | Bh 32K | Bl 32K = 96KB, x2 stages
#define ST_BYTES 98304
#define OFF_AH   0
#define OFF_AL   16384
#define OFF_BH   32768
#define OFF_BL   65536
#define SMEM_TOTAL (2 * ST_BYTES)

__device__ float g_logits[(size_t)TOKENS * NEXP];
__device__ float g_BhT[(size_t)NEXP * HIDDEN];   // tile-layout tf32 hi
__device__ float g_BlT[(size_t)NEXP * HIDDEN];   // tile-layout tf32 lo
__device__ int   g_nflag;
__device__ int   g_flagged[TOKENS];

// ---------------------------------------------------------------------------
__device__ __forceinline__ float tf32_rna(float x) {
    float r;
    asm("cvt.rna.tf32.f32 %0, %1;" : "=f"(r) : "f"(x));
    return r;
}

#define CPA16(dst, src) \
    asm volatile("cp.async.cg.shared.global [%0], [%1], 16;" \
                 :: "r"(dst), "l"(src) : "memory")

#define LDS128U(v, addr) \
    asm volatile("ld.shared.v4.u32 {%0,%1,%2,%3}, [%4];" \
                 : "=r"((v).x), "=r"((v).y), "=r"((v).z), "=r"((v).w) : "r"(addr))

#define STS128F(addr, a, b, c, d) \
    asm volatile("st.shared.v4.f32 [%0], {%1,%2,%3,%4};" \
                 :: "r"(addr), "f"(a), "f"(b), "f"(c), "f"(d) : "memory")

#define MMA_TF32(cp, A0, A1, A2, A3, B0, B1) \
    asm volatile("mma.sync.aligned.m16n8k8.row.col.f32.tf32.tf32.f32 " \
                 "{%0,%1,%2,%3}, {%4,%5,%6,%7}, {%8,%9}, {%0,%1,%2,%3};" \
                 : "+f"((cp)[0]), "+f"((cp)[1]), "+f"((cp)[2]), "+f"((cp)[3]) \
                 : "r"(A0), "r"(A1), "r"(A2), "r"(A3), "r"(B0), "r"(B1))

// ---------------------------------------------------------------------------
// Kernel 0: split W fp32 -> tf32 hi/lo in SMEM-tile byte layout.
// Tile layout per chunk (32KB): row n (128B): float at n*32 + c*8 + (h^(n&1))*4 + t4
// where source k = c + 16h + 4*t4.
// ---------------------------------------------------------------------------
__global__ __launch_bounds__(256)
void convert_b_kernel(const float* __restrict__ W) {
    if (blockIdx.x == 0 && threadIdx.x == 0) g_nflag = 0;  // reset per launch

    const int chunk = blockIdx.x;
    const int n     = threadIdx.x;
    const float* src = W + (size_t)n * HIDDEN + chunk * KC;

    float vv[32];
    #pragma unroll
    for (int t = 0; t < 8; t++) {
        float4 v = *(const float4*)(src + 4 * t);
        vv[4 * t + 0] = v.x; vv[4 * t + 1] = v.y;
        vv[4 * t + 2] = v.z; vv[4 * t + 3] = v.w;
    }
    float hi[32], lo[32];
    #pragma unroll
    for (int k = 0; k < 32; k++) {
        hi[k] = tf32_rna(vv[k]);
        lo[k] = tf32_rna(vv[k] - hi[k]);
    }
    float* dh = g_BhT + (size_t)chunk * (NEXP * KC) + n * 32;
    float* dl = g_BlT + (size_t)chunk * (NEXP * KC) + n * 32;
    #pragma unroll
    for (int c = 0; c < 4; c++) {
        #pragma unroll
        for (int h = 0; h < 2; h++) {
            const int off = c * 8 + ((h ^ (n & 1)) << 2);
            const int kb  = c + 16 * h;
            *(float4*)(dh + off) = make_float4(hi[kb], hi[kb + 4], hi[kb + 8], hi[kb + 12]);
            *(float4*)(dl + off) = make_float4(lo[kb], lo[kb + 4], lo[kb + 8], lo[kb + 12]);
        }
    }
}

// ---------------------------------------------------------------------------
// Kernel 1: 3xTF32 mma.sync GEMM (unchanged from R3; layout audited correct).
// ---------------------------------------------------------------------------
__global__ __launch_bounds__(256, 1)
void gemm_tc(const float* __restrict__ A)
{
    extern __shared__ char smem[];
    uint32_t sb;
    asm("{ .reg .u64 t; cvta.to.shared.u64 t, %1; cvt.u32.u64 %0, t; }"
        : "=r"(sb) : "l"((void*)smem));

    const int tid  = threadIdx.x;
    const int lane = tid & 31;
    const int wid  = tid >> 5;
    const int wm   = wid >> 2;
    const int wn   = wid & 3;
    const int lq   = lane >> 2;
    const int lr   = lane & 3;
    const int bm   = blockIdx.x * 128;

    const int am   = tid >> 1;
    const int ah   = tid & 1;
    const int arot = (lane >> 1) & 3;
    const float* Agp = A + (size_t)(bm + am) * HIDDEN + ah * 16;
    const int bn   = tid;

    float cc[4][8][4];
    #pragma unroll
    for (int i = 0; i < 4; i++)
        #pragma unroll
        for (int j = 0; j < 8; j++)
            #pragma unroll
            for (int q = 0; q < 4; q++) cc[i][j][q] = 0.0f;

#define LOAD_B_ASYNC(nc, st) do {                                              \
        const char* __sh = (const char*)(g_BhT + (size_t)(nc) * (NEXP * KC)) + bn * 128; \
        const char* __sl = (const char*)(g_BlT + (size_t)(nc) * (NEXP * KC)) + bn * 128; \
        uint32_t __dh = sb + (st) * ST_BYTES + OFF_BH + bn * 128;              \
        uint32_t __dl = sb + (st) * ST_BYTES + OFF_BL + bn * 128;              \
        _Pragma("unroll")                                                      \
        for (int g = 0; g < 8; g++) {                                          \
            CPA16(__dh + g * 16, __sh + g * 16);                               \
            CPA16(__dl + g * 16, __sl + g * 16);                               \
        }                                                                      \
        asm volatile("cp.async.commit_group;" ::: "memory");                   \
    } while (0)

#define LOAD_A_LDG(nc, av) do {                                                \
        _Pragma("unroll")                                                      \
        for (int s4i = 0; s4i < 4; s4i++) {                                    \
            const int cr = (s4i + arot) & 3;                                   \
            const float* __p = Agp + (size_t)(nc) * KC + cr;                   \
            _Pragma("unroll")                                                  \
            for (int t4 = 0; t4 < 4; t4++)                                     \
                (av)[s4i][t4] = __ldg(__p + 4 * t4);                           \
        }                                                                      \
    } while (0)

#define STORE_A_STS(st, av) do {                                               \
        const uint32_t __sd = sb + (st) * ST_BYTES;                            \
        _Pragma("unroll")                                                      \
        for (int s4i = 0; s4i < 4; s4i++) {                                    \
            const int cr = (s4i + arot) & 3;                                   \
            const uint32_t __off = am * 128 + cr * 32 + ((ah ^ (am & 1)) << 4);\
            float h0 = tf32_rna((av)[s4i][0]), h1 = tf32_rna((av)[s4i][1]);    \
            float h2 = tf32_rna((av)[s4i][2]), h3 = tf32_rna((av)[s4i][3]);    \
            STS128F(__sd + OFF_AH + __off, h0, h1, h2, h3);                    \
            STS128F(__sd + OFF_AL + __off,                                     \
                    tf32_rna((av)[s4i][0] - h0), tf32_rna((av)[s4i][1] - h1),  \
                    tf32_rna((av)[s4i][2] - h2), tf32_rna((av)[s4i][3] - h3)); \
        }                                                                      \
    } while (0)

    {
        LOAD_B_ASYNC(0, 0);
        float av[4][4];
        LOAD_A_LDG(0, av);
        STORE_A_STS(0, av);
        asm volatile("cp.async.wait_group 0;" ::: "memory");
        __syncthreads();
    }

#define LOAD_AF(off, base, H, a) do {                                          \
        _Pragma("unroll")                                                      \
        for (int mb = 0; mb < 4; mb++) {                                       \
            _Pragma("unroll")                                                  \
            for (int rh = 0; rh < 2; rh++) {                                   \
                const int r = wm * 64 + mb * 16 + lq + rh * 8;                 \
                const uint32_t ad = (base) + (off) + r * 128 + lr * 32 +       \
                                    (((H) ^ (lq & 1)) << 4);                   \
                LDS128U((a)[mb][rh], ad);                                      \
            }                                                                  \
        }                                                                      \
    } while (0)

#define LOAD_BF(off, base, H, b) do {                                          \
        _Pragma("unroll")                                                      \
        for (int nb = 0; nb < 8; nb++) {                                       \
            const int n = wn * 64 + nb * 8 + lq;                               \
            const uint32_t ad = (base) + (off) + n * 128 + lr * 32 +           \
                                (((H) ^ (lq & 1)) << 4);                       \
            LDS128U((b)[nb], ad);                                              \
        }                                                                      \
    } while (0)

#define MMA_SET(a, b) do {                                                     \
        _Pragma("unroll")                                                      \
        for (int mb = 0; mb < 4; mb++) {                                       \
            _Pragma("unroll")                                                  \
            for (int nb = 0; nb < 8; nb++) {                                   \
                MMA_TF32(cc[mb][nb], (a)[mb][0].x, (a)[mb][1].x,               \
                         (a)[mb][0].y, (a)[mb][1].y, (b)[nb].x, (b)[nb].y);    \
                MMA_TF32(cc[mb][nb], (a)[mb][0].z, (a)[mb][1].z,               \
                         (a)[mb][0].w, (a)[mb][1].w, (b)[nb].z, (b)[nb].w);    \
            }                                                                  \
        }                                                                      \
    } while (0)

    for (int c = 0; c < NCHUNK; c++) {
        const int s  = c & 1;
        const bool np = (c + 1 < NCHUNK);
        float av[4][4];
        if (np) {
            LOAD_B_ASYNC(c + 1, s ^ 1);
            LOAD_A_LDG(c + 1, av);
        }

        const uint32_t base = sb + s * ST_BYTES;
        #pragma unroll
        for (int H = 0; H < 2; H++) {
            uint4 a[4][2], b[8];
            LOAD_AF(OFF_AH, base, H, a);
            LOAD_BF(OFF_BH, base, H, b);
            MMA_SET(a, b);                    // Ah*Bh
            LOAD_AF(OFF_AL, base, H, a);
            MMA_SET(a, b);                    // Al*Bh
            LOAD_BF(OFF_BL, base, H, b);
            LOAD_AF(OFF_AH, base, H, a);
            MMA_SET(a, b);                    // Ah*Bl
        }

        if (np) {
            STORE_A_STS(s ^ 1, av);
            asm volatile("cp.async.wait_group 0;" ::: "memory");
        }
        __syncthreads();
    }

    #pragma unroll
    for (int mb = 0; mb < 4; mb++) {
        const int r0 = bm + wm * 64 + mb * 16 + lq;
        #pragma unroll
        for (int nb = 0; nb < 8; nb++) {
            const int col = wn * 64 + nb * 8 + 2 * lr;
            *(float2*)(g_logits + (size_t)r0 * NEXP + col) =
                make_float2(cc[mb][nb][0], cc[mb][nb][1]);
            *(float2*)(g_logits + (size_t)(r0 + 8) * NEXP + col) =
                make_float2(cc[mb][nb][2], cc[mb][nb][3]);
        }
    }
}

// ---------------------------------------------------------------------------
// route_one: full routing for one token from a 256-logit row (global or smem).
// Matches jax reference exactly: mask non-selected groups to 0.0 (score*mask),
// stable tie-breaking (lowest index). If do_flag, computes selection-stability
// margins and pushes the token onto the recompute list when any margin < TAU.
// ---------------------------------------------------------------------------
__device__ __forceinline__ void route_one(const float* __restrict__ row,
                                          const float* __restrict__ bias,
                                          float* __restrict__ out,
                                          int write_idx, int token, int lane,
                                          int do_flag)
{
    const unsigned FULL = 0xffffffffu;

    float4 l0 = *(const float4*)(row + lane * 8);
    float4 l1 = *(const float4*)(row + lane * 8 + 4);
    float4 b0 = *(const float4*)(bias + lane * 8);
    float4 b1 = *(const float4*)(bias + lane * 8 + 4);

    float lv[8] = {l0.x, l0.y, l0.z, l0.w, l1.x, l1.y, l1.z, l1.w};
    float bb[8] = {b0.x, b0.y, b0.z, b0.w, b1.x, b1.y, b1.z, b1.w};
    float sc[8], s4[8];
    #pragma unroll
    for (int i = 0; i < 8; i++) {
        float s = 1.0f / (1.0f + expf(-lv[i]));
        sc[i] = s;
        s4[i] = s + bb[i];
    }

    // ---- per-lane top-3, merged across the 4 lanes of the group ----
    float m1 = -CUDART_INF_F, m2 = -CUDART_INF_F, m3 = -CUDART_INF_F;
    #pragma unroll
    for (int i = 0; i < 8; i++) {
        float v = s4[i];
        if (v > m1)      { m3 = m2; m2 = m1; m1 = v; }
        else if (v > m2) { m3 = m2; m2 = v; }
        else if (v > m3) { m3 = v; }
    }
    #pragma unroll
    for (int d = 1; d <= 2; d <<= 1) {
        float o1 = __shfl_xor_sync(FULL, m1, d);
        float o2 = __shfl_xor_sync(FULL, m2, d);
        float o3 = __shfl_xor_sync(FULL, m3, d);
        float mn1 = fminf(m1, o1);
        float mx2 = fmaxf(m2, o2);
        float n1 = fmaxf(m1, o1);
        float n2 = fmaxf(mn1, mx2);
        float n3 = fmaxf(fminf(mn1, mx2), fmaxf(m3, o3));
        m1 = n1; m2 = n2; m3 = n3;
    }
    const float gs  = m1 + m2;   // group score
    const float m23 = m2 - m3;   // margin: group-score composition stability
    const int   g   = lane >> 2;

    int rank = 0;
    #pragma unroll
    for (int j = 0; j < 8; j++) {
        float gj = __shfl_sync(FULL, gs, j * 4);
        rank += (gj > gs) || (gj == gs && j < g);
    }
    const int selg = (rank < 4);
    if (!selg) {
        #pragma unroll
        for (int i = 0; i < 8; i++) s4[i] = 0.0f;   // reference: score * mask
    }

    float flagmin = CUDART_INF_F;
    if (do_flag) {
        float vsel = selg ? gs : CUDART_INF_F;
        float vuns = selg ? -CUDART_INF_F : gs;
        float mm   = m23;
        #pragma unroll
        for (int d = 16; d; d >>= 1) {
            vsel = fminf(vsel, __shfl_xor_sync(FULL, vsel, d));
            vuns = fmaxf(vuns, __shfl_xor_sync(FULL, vuns, d));
            mm   = fminf(mm,   __shfl_xor_sync(FULL, mm,   d));
        }
        flagmin = fminf(vsel - vuns, mm);   // group-4/5 gap, top2/3 gaps
    }

    // ---- global top-8 (ties -> lower expert index), track consecutive gaps ----
    float wsum = 0.0f, my_w = 0.0f, prevv = 0.0f;
    int   my_ix = 0;
    #pragma unroll
    for (int t = 0; t < 8; t++) {
        float bv = s4[0]; int bp = 0;
        #pragma unroll
        for (int i = 1; i < 8; i++)
            if (s4[i] > bv) { bv = s4[i]; bp = i; }
        float v  = bv;
        int   ix = lane * 8 + bp;
        #pragma unroll
        for (int d = 16; d; d >>= 1) {
            float ov = __shfl_xor_sync(FULL, v, d);
            int   oi = __shfl_xor_sync(FULL, ix, d);
            if (ov > v || (ov == v && oi < ix)) { v = ov; ix = oi; }
        }
        if (t > 0) flagmin = fminf(flagmin, prevv - v);
        prevv = v;
        const int opos  = ix & 7;
        const int olane = ix >> 3;
        #pragma unroll
        for (int i = 0; i < 8; i++)
            if (lane == olane && i == opos) s4[i] = -CUDART_INF_F;
        float cand = sc[0];
        #pragma unroll
        for (int i = 1; i < 8; i++)
            if (i == opos) cand = sc[i];
        float w = __shfl_sync(FULL, cand, olane);
        wsum += w;
        if (lane == t) { my_w = w; my_ix = ix; }
    }

    if (do_flag) {
        // 9th-best value for the final selection margin
        float bv = s4[0];
        #pragma unroll
        for (int i = 1; i < 8; i++) bv = fmaxf(bv, s4[i]);
        #pragma unroll
        for (int d = 16; d; d >>= 1)
            bv = fmaxf(bv, __shfl_xor_sync(FULL, bv, d));
        flagmin = fminf(flagmin, prevv - bv);
        if (lane == 0 && flagmin < TAU) {
            int p = atomicAdd(&g_nflag, 1);
            g_flagged[p] = token;
        }
    }

    const float scale = 2.5f / (wsum + 1e-20f);
    if (lane < TOPK) {
        out[(size_t)token * TOPK + lane] = my_w * scale;
        if (write_idx)
            out[(size_t)TOKENS * TOPK + (size_t)token * TOPK + lane] = (float)my_ix;
    }
}

// ---------------------------------------------------------------------------
// Kernel 2: routing from tf32 logits, with margin flagging.
// ---------------------------------------------------------------------------
__global__ __launch_bounds__(256)
void routing_kernel(const float* __restrict__ bias, float* __restrict__ out,
                    int write_idx)
{
    const int lane  = threadIdx.x & 31;
    const int warp  = threadIdx.x >> 5;
    const int token = blockIdx.x * 8 + warp;
    route_one(g_logits + (size_t)token * NEXP, bias, out, write_idx, token,
              lane, 1);
}

// ---------------------------------------------------------------------------
// Kernel 3: fp32 recompute + re-route for flagged tokens.
// ---------------------------------------------------------------------------
__global__ __launch_bounds__(256)
void recompute_kernel(const float* __restrict__ A, const float* __restrict__ W,
                      const float* __restrict__ bias, float* __restrict__ out,
                      int write_idx)
{
    __shared__ __align__(16) float srow[HIDDEN];
    __shared__ __align__(16) float slog[NEXP];

    const int nf   = g_nflag;
    const int wid  = threadIdx.x >> 5;
    const int lane = threadIdx.x & 31;

    for (int it = blockIdx.x; it < nf; it += gridDim.x) {
        const int token = g_flagged[it];
        for (int i = threadIdx.x * 4; i < HIDDEN; i += 1024)
            *(float4*)(srow + i) = *(const float4*)(A + (size_t)token * HIDDEN + i);
        __syncthreads();

        for (int e = wid * 32; e < wid * 32 + 32; e++) {
            const float* wr = W + (size_t)e * HIDDEN;
            float a0 = 0.f, a1 = 0.f;
            for (int i = lane * 4; i < HIDDEN; i += 256) {
                float4 wv = *(const float4*)(wr + i);
                float4 av = *(const float4*)(srow + i);
                a0 += av.x * wv.x + av.y * wv.y + av.z * wv.z + av.w * wv.w;
                float4 wv2 = *(const float4*)(wr + i + 128);
                float4 av2 = *(const float4*)(srow + i + 128);
                a1 += av2.x * wv2.x + av2.y * wv2.y + av2.z * wv2.z + av2.w * wv2.w;
            }
            float acc = a0 + a1;
            #pragma unroll
            for (int d = 16; d; d >>= 1)
                acc += __shfl_xor_sync(0xffffffffu, acc, d);
            if (lane == 0) slog[e] = acc;
        }
        __syncthreads();

        if (wid == 0)
            route_one(slog, bias, out, write_idx, token, lane, 0);
        __syncthreads();
    }
}

// ---------------------------------------------------------------------------
extern "C" void kernel_launch(void* const* d_in, const int* in_sizes, int n_in,
                              void* d_out, int out_size)
{
    const float* hs   = (const float*)d_in[0];  // [16384, 7168]
    const float* w    = (const float*)d_in[1];  // [256, 7168]
    const float* bias = (const float*)d_in[2];  // [256]
    float* out = (float*)d_out;

    cudaFuncSetAttribute(gemm_tc, cudaFuncAttributeMaxDynamicSharedMemorySize,
                         SMEM_TOTAL);

    convert_b_kernel<<<NCHUNK, 256>>>(w);
    gemm_tc<<<TOKENS / 128, 256, SMEM_TOTAL>>>(hs);

    const int write_idx = (out_size >= TOKENS * TOPK * 2) ? 1 : 0;
    routing_kernel<<<TOKENS / 8, 256>>>(bias, out, write_idx);
    recompute_kernel<<<128, 256>>>(hs, w, bias, out, write_idx);
}

// round 5
// speedup vs baseline: 1.0416x; 1.0416x over previous
#include <cuda_runtime.h>
#include <math_constants.h>
#include <math.h>
#include <cstdint>

#define TOKENS 16384
#define HIDDEN 7168
#define NEXP   256
#define TOPK   8
#define KC     32
#define NCHUNK (HIDDEN / KC)   // 224
#define TAU    1e-4f

// SMEM stage layout (bytes): Ah 16K | Al 16K | Bh 16K | Bl 16K = 64KB, x2 stages
#define ST_BYTES 65536
#define OFF_AH   0
#define OFF_AL   16384
#define OFF_BH   32768
#define OFF_BL   49152
#define SMEM_TOTAL (2 * ST_BYTES)

__device__ float g_logits[(size_t)TOKENS * NEXP];
__device__ float g_BhT[(size_t)NEXP * HIDDEN];   // tile-layout tf32 hi
__device__ float g_BlT[(size_t)NEXP * HIDDEN];   // tile-layout tf32 lo
__device__ int   g_nflag;
__device__ int   g_flagged[TOKENS];

// ---------------------------------------------------------------------------
__device__ __forceinline__ float tf32_rna(float x) {
    float r;
    asm("cvt.rna.tf32.f32 %0, %1;" : "=f"(r) : "f"(x));
    return r;
}

#define CPA16(dst, src) \
    asm volatile("cp.async.cg.shared.global [%0], [%1], 16;" \
                 :: "r"(dst), "l"(src) : "memory")

#define LDS128U(v, addr) \
    asm volatile("ld.shared.v4.u32 {%0,%1,%2,%3}, [%4];" \
                 : "=r"((v).x), "=r"((v).y), "=r"((v).z), "=r"((v).w) : "r"(addr))

#define STS128F(addr, a, b, c, d) \
    asm volatile("st.shared.v4.f32 [%0], {%1,%2,%3,%4};" \
                 :: "r"(addr), "f"(a), "f"(b), "f"(c), "f"(d) : "memory")

#define MMA_TF32(cp, A0, A1, A2, A3, B0, B1) \
    asm volatile("mma.sync.aligned.m16n8k8.row.col.f32.tf32.tf32.f32 " \
                 "{%0,%1,%2,%3}, {%4,%5,%6,%7}, {%8,%9}, {%0,%1,%2,%3};" \
                 : "+f"((cp)[0]), "+f"((cp)[1]), "+f"((cp)[2]), "+f"((cp)[3]) \
                 : "r"(A0), "r"(A1), "r"(A2), "r"(A3), "r"(B0), "r"(B1))

// ---------------------------------------------------------------------------
// Kernel 0: split W fp32 -> tf32 hi/lo in SMEM-tile byte layout.
// Tile layout per chunk (32KB over 256 rows): row n (128B):
//   float at n*32 + c*8 + (h^(n&1))*4 + t4, where source k = c + 16h + 4*t4.
// ---------------------------------------------------------------------------
__global__ __launch_bounds__(256)
void convert_b_kernel(const float* __restrict__ W) {
    if (blockIdx.x == 0 && threadIdx.x == 0) g_nflag = 0;  // reset per launch

    const int chunk = blockIdx.x;
    const int n     = threadIdx.x;
    const float* src = W + (size_t)n * HIDDEN + chunk * KC;

    float vv[32];
    #pragma unroll
    for (int t = 0; t < 8; t++) {
        float4 v = *(const float4*)(src + 4 * t);
        vv[4 * t + 0] = v.x; vv[4 * t + 1] = v.y;
        vv[4 * t + 2] = v.z; vv[4 * t + 3] = v.w;
    }
    float hi[32], lo[32];
    #pragma unroll
    for (int k = 0; k < 32; k++) {
        hi[k] = tf32_rna(vv[k]);
        lo[k] = tf32_rna(vv[k] - hi[k]);
    }
    float* dh = g_BhT + (size_t)chunk * (NEXP * KC) + n * 32;
    float* dl = g_BlT + (size_t)chunk * (NEXP * KC) + n * 32;
    #pragma unroll
    for (int c = 0; c < 4; c++) {
        #pragma unroll
        for (int h = 0; h < 2; h++) {
            const int off = c * 8 + ((h ^ (n & 1)) << 2);
            const int kb  = c + 16 * h;
            *(float4*)(dh + off) = make_float4(hi[kb], hi[kb + 4], hi[kb + 8], hi[kb + 12]);
            *(float4*)(dl + off) = make_float4(lo[kb], lo[kb + 4], lo[kb + 8], lo[kb + 12]);
        }
    }
}

// ---------------------------------------------------------------------------
// Kernel 1: 3xTF32 mma.sync GEMM. CTA = 128 tokens x 128 experts (grid 128x2),
// 8 warps in 4x2, warp tile 32x64 -> 64 accum regs/thread (no spills).
// ---------------------------------------------------------------------------
__global__ __launch_bounds__(256, 1)
void gemm_tc(const float* __restrict__ A)
{
    extern __shared__ char smem[];
    uint32_t sb;
    asm("{ .reg .u64 t; cvta.to.shared.u64 t, %1; cvt.u32.u64 %0, t; }"
        : "=r"(sb) : "l"((void*)smem));

    const int tid  = threadIdx.x;
    const int lane = tid & 31;
    const int wid  = tid >> 5;
    const int wm   = wid >> 1;          // 0..3  (32-row band)
    const int wn   = wid & 1;           // 0..1  (64-col band)
    const int lq   = lane >> 2;         // 0..7
    const int lr   = lane & 3;          // 0..3
    const int bm   = blockIdx.x * 128;
    const int bnb  = blockIdx.y * 128;  // expert block base

    // A loader roles (128 rows, 2 threads/row)
    const int am   = tid >> 1;
    const int ah   = tid & 1;
    const int arot = (lane >> 1) & 3;
    const float* Agp = A + (size_t)(bm + am) * HIDDEN + ah * 16;
    // B loader roles (128 rows, 2 threads/row, 64B halves)
    const int brow = tid >> 1;
    const int bhalf = tid & 1;
    // source float offset within chunk tile for this CTA's expert block
    const size_t boff = (size_t)(bnb + brow) * KC + bhalf * 16;

    float cc[2][8][4];
    #pragma unroll
    for (int i = 0; i < 2; i++)
        #pragma unroll
        for (int j = 0; j < 8; j++)
            #pragma unroll
            for (int q = 0; q < 4; q++) cc[i][j][q] = 0.0f;

#define LOAD_B_ASYNC(nc, st) do {                                              \
        const float* __sh = g_BhT + (size_t)(nc) * (NEXP * KC) + boff;         \
        const float* __sl = g_BlT + (size_t)(nc) * (NEXP * KC) + boff;         \
        uint32_t __dh = sb + (st) * ST_BYTES + OFF_BH + brow * 128 + bhalf * 64; \
        uint32_t __dl = sb + (st) * ST_BYTES + OFF_BL + brow * 128 + bhalf * 64; \
        _Pragma("unroll")                                                      \
        for (int g = 0; g < 4; g++) {                                          \
            CPA16(__dh + g * 16, __sh + g * 4);                                \
            CPA16(__dl + g * 16, __sl + g * 4);                                \
        }                                                                      \
        asm volatile("cp.async.commit_group;" ::: "memory");                   \
    } while (0)

#define LOAD_A_LDG(nc, av) do {                                                \
        _Pragma("unroll")                                                      \
        for (int s4i = 0; s4i < 4; s4i++) {                                    \
            const int cr = (s4i + arot) & 3;                                   \
            const float* __p = Agp + (size_t)(nc) * KC + cr;                   \
            _Pragma("unroll")                                                  \
            for (int t4 = 0; t4 < 4; t4++)                                     \
                (av)[s4i][t4] = __ldg(__p + 4 * t4);                           \
        }                                                                      \
    } while (0)

#define STORE_A_STS(st, av) do {                                               \
        const uint32_t __sd = sb + (st) * ST_BYTES;                            \
        _Pragma("unroll")                                                      \
        for (int s4i = 0; s4i < 4; s4i++) {                                    \
            const int cr = (s4i + arot) & 3;                                   \
            const uint32_t __off = am * 128 + cr * 32 + ((ah ^ (am & 1)) << 4);\
            float h0 = tf32_rna((av)[s4i][0]), h1 = tf32_rna((av)[s4i][1]);    \
            float h2 = tf32_rna((av)[s4i][2]), h3 = tf32_rna((av)[s4i][3]);    \
            STS128F(__sd + OFF_AH + __off, h0, h1, h2, h3);                    \
            STS128F(__sd + OFF_AL + __off,                                     \
                    tf32_rna((av)[s4i][0] - h0), tf32_rna((av)[s4i][1] - h1),  \
                    tf32_rna((av)[s4i][2] - h2), tf32_rna((av)[s4i][3] - h3)); \
        }                                                                      \
    } while (0)

    // ---- prologue: stage 0 ----
    {
        LOAD_B_ASYNC(0, 0);
        float av[4][4];
        LOAD_A_LDG(0, av);
        STORE_A_STS(0, av);
        asm volatile("cp.async.wait_group 0;" ::: "memory");
        __syncthreads();
    }

#define LOAD_AF(off, base, H, a) do {                                          \
        _Pragma("unroll")                                                      \
        for (int mb = 0; mb < 2; mb++) {                                       \
            _Pragma("unroll")                                                  \
            for (int rh = 0; rh < 2; rh++) {                                   \
                const int r = wm * 32 + mb * 16 + lq + rh * 8;                 \
                const uint32_t ad = (base) + (off) + r * 128 + lr * 32 +       \
                                    (((H) ^ (lq & 1)) << 4);                   \
                LDS128U((a)[mb][rh], ad);                                      \
            }                                                                  \
        }                                                                      \
    } while (0)

#define LOAD_BF(off, base, H, b) do {                                          \
        _Pragma("unroll")                                                      \
        for (int nb = 0; nb < 8; nb++) {                                       \
            const int n = wn * 64 + nb * 8 + lq;                               \
            const uint32_t ad = (base) + (off) + n * 128 + lr * 32 +           \
                                (((H) ^ (lq & 1)) << 4);                       \
            LDS128U((b)[nb], ad);                                              \
        }                                                                      \
    } while (0)

#define MMA_SET(a, b) do {                                                     \
        _Pragma("unroll")                                                      \
        for (int mb = 0; mb < 2; mb++) {                                       \
            _Pragma("unroll")                                                  \
            for (int nb = 0; nb < 8; nb++) {                                   \
                MMA_TF32(cc[mb][nb], (a)[mb][0].x, (a)[mb][1].x,               \
                         (a)[mb][0].y, (a)[mb][1].y, (b)[nb].x, (b)[nb].y);    \
                MMA_TF32(cc[mb][nb], (a)[mb][0].z, (a)[mb][1].z,               \
                         (a)[mb][0].w, (a)[mb][1].w, (b)[nb].z, (b)[nb].w);    \
            }                                                                  \
        }                                                                      \
    } while (0)

    // ---- main loop ----
    for (int c = 0; c < NCHUNK; c++) {
        const int s  = c & 1;
        const bool np = (c + 1 < NCHUNK);
        float av[4][4];
        if (np) {
            LOAD_B_ASYNC(c + 1, s ^ 1);
            LOAD_A_LDG(c + 1, av);    // held in regs across compute
        }

        const uint32_t base = sb + s * ST_BYTES;
        #pragma unroll
        for (int H = 0; H < 2; H++) {
            uint4 ahh[2][2], all[2][2], b[8];
            LOAD_AF(OFF_AH, base, H, ahh);
            LOAD_AF(OFF_AL, base, H, all);
            LOAD_BF(OFF_BH, base, H, b);
            MMA_SET(ahh, b);                  // Ah*Bh
            MMA_SET(all, b);                  // Al*Bh
            LOAD_BF(OFF_BL, base, H, b);
            MMA_SET(ahh, b);                  // Ah*Bl
        }

        if (np) {
            STORE_A_STS(s ^ 1, av);
            asm volatile("cp.async.wait_group 0;" ::: "memory");
        }
        __syncthreads();
    }

    // ---- epilogue ----
    #pragma unroll
    for (int mb = 0; mb < 2; mb++) {
        const int r0 = bm + wm * 32 + mb * 16 + lq;
        #pragma unroll
        for (int nb = 0; nb < 8; nb++) {
            const int col = bnb + wn * 64 + nb * 8 + 2 * lr;
            *(float2*)(g_logits + (size_t)r0 * NEXP + col) =
                make_float2(cc[mb][nb][0], cc[mb][nb][1]);
            *(float2*)(g_logits + (size_t)(r0 + 8) * NEXP + col) =
                make_float2(cc[mb][nb][2], cc[mb][nb][3]);
        }
    }
}

// ---------------------------------------------------------------------------
// route_one: full routing for one token (reference-exact; see R4).
// ---------------------------------------------------------------------------
__device__ __forceinline__ void route_one(const float* __restrict__ row,
                                          const float* __restrict__ bias,
                                          float* __restrict__ out,
                                          int write_idx, int token, int lane,
                                          int do_flag)
{
    const unsigned FULL = 0xffffffffu;

    float4 l0 = *(const float4*)(row + lane * 8);
    float4 l1 = *(const float4*)(row + lane * 8 + 4);
    float4 b0 = *(const float4*)(bias + lane * 8);
    float4 b1 = *(const float4*)(bias + lane * 8 + 4);

    float lv[8] = {l0.x, l0.y, l0.z, l0.w, l1.x, l1.y, l1.z, l1.w};
    float bb[8] = {b0.x, b0.y, b0.z, b0.w, b1.x, b1.y, b1.z, b1.w};
    float sc[8], s4[8];
    #pragma unroll
    for (int i = 0; i < 8; i++) {
        float s = 1.0f / (1.0f + expf(-lv[i]));
        sc[i] = s;
        s4[i] = s + bb[i];
    }

    float m1 = -CUDART_INF_F, m2 = -CUDART_INF_F, m3 = -CUDART_INF_F;
    #pragma unroll
    for (int i = 0; i < 8; i++) {
        float v = s4[i];
        if (v > m1)      { m3 = m2; m2 = m1; m1 = v; }
        else if (v > m2) { m3 = m2; m2 = v; }
        else if (v > m3) { m3 = v; }
    }
    #pragma unroll
    for (int d = 1; d <= 2; d <<= 1) {
        float o1 = __shfl_xor_sync(FULL, m1, d);
        float o2 = __shfl_xor_sync(FULL, m2, d);
        float o3 = __shfl_xor_sync(FULL, m3, d);
        float mn1 = fminf(m1, o1);
        float mx2 = fmaxf(m2, o2);
        float n1 = fmaxf(m1, o1);
        float n2 = fmaxf(mn1, mx2);
        float n3 = fmaxf(fminf(mn1, mx2), fmaxf(m3, o3));
        m1 = n1; m2 = n2; m3 = n3;
    }
    const float gs  = m1 + m2;
    const float m23 = m2 - m3;
    const int   g   = lane >> 2;

    int rank = 0;
    #pragma unroll
    for (int j = 0; j < 8; j++) {
        float gj = __shfl_sync(FULL, gs, j * 4);
        rank += (gj > gs) || (gj == gs && j < g);
    }
    const int selg = (rank < 4);
    if (!selg) {
        #pragma unroll
        for (int i = 0; i < 8; i++) s4[i] = 0.0f;   // reference: score * mask
    }

    float flagmin = CUDART_INF_F;
    if (do_flag) {
        float vsel = selg ? gs : CUDART_INF_F;
        float vuns = selg ? -CUDART_INF_F : gs;
        float mm   = m23;
        #pragma unroll
        for (int d = 16; d; d >>= 1) {
            vsel = fminf(vsel, __shfl_xor_sync(FULL, vsel, d));
            vuns = fmaxf(vuns, __shfl_xor_sync(FULL, vuns, d));
            mm   = fminf(mm,   __shfl_xor_sync(FULL, mm,   d));
        }
        flagmin = fminf(vsel - vuns, mm);
    }

    float wsum = 0.0f, my_w = 0.0f, prevv = 0.0f;
    int   my_ix = 0;
    #pragma unroll
    for (int t = 0; t < 8; t++) {
        float bv = s4[0]; int bp = 0;
        #pragma unroll
        for (int i = 1; i < 8; i++)
            if (s4[i] > bv) { bv = s4[i]; bp = i; }
        float v  = bv;
        int   ix = lane * 8 + bp;
        #pragma unroll
        for (int d = 16; d; d >>= 1) {
            float ov = __shfl_xor_sync(FULL, v, d);
            int   oi = __shfl_xor_sync(FULL, ix, d);
            if (ov > v || (ov == v && oi < ix)) { v = ov; ix = oi; }
        }
        if (t > 0) flagmin = fminf(flagmin, prevv - v);
        prevv = v;
        const int opos  = ix & 7;
        const int olane = ix >> 3;
        #pragma unroll
        for (int i = 0; i < 8; i++)
            if (lane == olane && i == opos) s4[i] = -CUDART_INF_F;
        float cand = sc[0];
        #pragma unroll
        for (int i = 1; i < 8; i++)
            if (i == opos) cand = sc[i];
        float w = __shfl_sync(FULL, cand, olane);
        wsum += w;
        if (lane == t) { my_w = w; my_ix = ix; }
    }

    if (do_flag) {
        float bv = s4[0];
        #pragma unroll
        for (int i = 1; i < 8; i++) bv = fmaxf(bv, s4[i]);
        #pragma unroll
        for (int d = 16; d; d >>= 1)
            bv = fmaxf(bv, __shfl_xor_sync(FULL, bv, d));
        flagmin = fminf(flagmin, prevv - bv);
        if (lane == 0 && flagmin < TAU) {
            int p = atomicAdd(&g_nflag, 1);
            g_flagged[p] = token;
        }
    }

    const float scale = 2.5f / (wsum + 1e-20f);
    if (lane < TOPK) {
        out[(size_t)token * TOPK + lane] = my_w * scale;
        if (write_idx)
            out[(size_t)TOKENS * TOPK + (size_t)token * TOPK + lane] = (float)my_ix;
    }
}

// ---------------------------------------------------------------------------
__global__ __launch_bounds__(256)
void routing_kernel(const float* __restrict__ bias, float* __restrict__ out,
                    int write_idx)
{
    const int lane  = threadIdx.x & 31;
    const int warp  = threadIdx.x >> 5;
    const int token = blockIdx.x * 8 + warp;
    route_one(g_logits + (size_t)token * NEXP, bias, out, write_idx, token,
              lane, 1);
}

// ---------------------------------------------------------------------------
__global__ __launch_bounds__(256)
void recompute_kernel(const float* __restrict__ A, const float* __restrict__ W,
                      const float* __restrict__ bias, float* __restrict__ out,
                      int write_idx)
{
    __shared__ __align__(16) float srow[HIDDEN];
    __shared__ __align__(16) float slog[NEXP];

    const int nf   = g_nflag;
    const int wid  = threadIdx.x >> 5;
    const int lane = threadIdx.x & 31;

    for (int it = blockIdx.x; it < nf; it += gridDim.x) {
        const int token = g_flagged[it];
        for (int i = threadIdx.x * 4; i < HIDDEN; i += 1024)
            *(float4*)(srow + i) = *(const float4*)(A + (size_t)token * HIDDEN + i);
        __syncthreads();

        for (int e = wid * 32; e < wid * 32 + 32; e++) {
            const float* wr = W + (size_t)e * HIDDEN;
            float a0 = 0.f, a1 = 0.f;
            for (int i = lane * 4; i < HIDDEN; i += 256) {
                float4 wv = *(const float4*)(wr + i);
                float4 av = *(const float4*)(srow + i);
                a0 += av.x * wv.x + av.y * wv.y + av.z * wv.z + av.w * wv.w;
                float4 wv2 = *(const float4*)(wr + i + 128);
                float4 av2 = *(const float4*)(srow + i + 128);
                a1 += av2.x * wv2.x + av2.y * wv2.y + av2.z * wv2.z + av2.w * wv2.w;
            }
            float acc = a0 + a1;
            #pragma unroll
            for (int d = 16; d; d >>= 1)
                acc += __shfl_xor_sync(0xffffffffu, acc, d);
            if (lane == 0) slog[e] = acc;
        }
        __syncthreads();

        if (wid == 0)
            route_one(slog, bias, out, write_idx, token, lane, 0);
        __syncthreads();
    }
}

// ---------------------------------------------------------------------------
extern "C" void kernel_launch(void* const* d_in, const int* in_sizes, int n_in,
                              void* d_out, int out_size)
{
    const float* hs   = (const float*)d_in[0];  // [16384, 7168]
    const float* w    = (const float*)d_in[1];  // [256, 7168]
    const float* bias = (const float*)d_in[2];  // [256]
    float* out = (float*)d_out;

    cudaFuncSetAttribute(gemm_tc, cudaFuncAttributeMaxDynamicSharedMemorySize,
                         SMEM_TOTAL);

    convert_b_kernel<<<NCHUNK, 256>>>(w);
    dim3 ggrid(TOKENS / 128, NEXP / 128);   // (128, 2)
    gemm_tc<<<ggrid, 256, SMEM_TOTAL>>>(hs);

    const int write_idx = (out_size >= TOKENS * TOPK * 2) ? 1 : 0;
    routing_kernel<<<TOKENS / 8, 256>>>(bias, out, write_idx);
    recompute_kernel<<<128, 256>>>(hs, w, bias, out, write_idx);
}